// round 2
// baseline (speedup 1.0000x reference)
#include <cuda_runtime.h>
#include <math_constants.h>
#include <stdint.h>

#define B_    2
#define C_    128
#define N_    4096
#define GR_   32
#define CPG_  4
#define NH_   4
#define HD_   32
#define TK_   256
#define EPS_  1e-5f
#define SCALE_ 0.17677669529663689f   // 32^-0.5

// -------- scratch (device globals; no allocation allowed) --------
static __device__ float g_h[B_*C_*N_];                 // 4 MB groupnorm output
static __device__ float g_q[B_*NH_*N_*HD_];            // 4 MB  (b,h,n,d)
static __device__ float g_k[B_*NH_*N_*HD_];            // 4 MB
static __device__ float g_v[B_*NH_*N_*HD_];            // 4 MB
static __device__ float g_att[B_*C_*N_];               // 4 MB  (b,c,n)
static __device__ float g_scores[(size_t)B_*NH_*N_*N_];// 512 MB (bh,n,j)

__device__ __forceinline__ unsigned ordf(float f) {
    unsigned u = __float_as_uint(f);
    return (u & 0x80000000u) ? ~u : (u | 0x80000000u);   // monotonic float->uint
}

// ================= GroupNorm =================
// grid: 64 = B*GR, block 256
__global__ void __launch_bounds__(256) gn_kernel(const float* __restrict__ x,
                                                 const float* __restrict__ w,
                                                 const float* __restrict__ b) {
    int bg = blockIdx.x;
    int bb = bg / GR_, g = bg % GR_;
    const float* xp = x + ((size_t)bb*C_ + g*CPG_) * N_;
    float*       hp = g_h + ((size_t)bb*C_ + g*CPG_) * N_;
    int tid = threadIdx.x;

    float s = 0.f, s2 = 0.f;
    for (int i = tid; i < CPG_*N_; i += 256) {
        float v = xp[i];
        s += v; s2 += v*v;
    }
    __shared__ float rs[8], rs2[8];
    __shared__ float mu_s, rstd_s;
    #pragma unroll
    for (int o = 16; o; o >>= 1) {
        s  += __shfl_down_sync(0xffffffffu, s,  o);
        s2 += __shfl_down_sync(0xffffffffu, s2, o);
    }
    if ((tid & 31) == 0) { rs[tid>>5] = s; rs2[tid>>5] = s2; }
    __syncthreads();
    if (tid == 0) {
        float t = 0.f, t2 = 0.f;
        #pragma unroll
        for (int i = 0; i < 8; i++) { t += rs[i]; t2 += rs2[i]; }
        float inv = 1.f / (float)(CPG_*N_);
        float mu = t * inv;
        float var = t2 * inv - mu*mu;
        mu_s = mu;
        rstd_s = rsqrtf(var + EPS_);
    }
    __syncthreads();
    float mu = mu_s, rstd = rstd_s;
    for (int i = tid; i < CPG_*N_; i += 256) {
        int c = g*CPG_ + i / N_;
        hp[i] = (xp[i] - mu) * rstd * w[c] + b[c];
    }
}

// ================= QKV GEMM =================
// grid (N/64, B), block 256.  out o = which*128 + head*32 + d
// each thread: 6 o's (stride 64) x 16 n's
__global__ void __launch_bounds__(256) qkv_kernel(const float* __restrict__ W,
                                                  const float* __restrict__ bias) {
    __shared__ float hs[C_*64];   // [c][n_local], 32 KB
    int n0 = blockIdx.x * 64;
    int bb = blockIdx.y;
    int tid = threadIdx.x;
    const float* hp = g_h + (size_t)bb * C_ * N_;
    for (int i = tid; i < C_*64; i += 256) {
        int c = i >> 6, nl = i & 63;
        hs[i] = hp[(size_t)c*N_ + n0 + nl];
    }
    __syncthreads();

    int nq = tid & 3;       // n quad: n = nq*16 .. +15
    int og = tid >> 2;      // 0..63 ; o = og + 64*k, k<6
    float acc[6][16];
    #pragma unroll
    for (int k = 0; k < 6; k++)
        #pragma unroll
        for (int j = 0; j < 16; j++) acc[k][j] = 0.f;

    const float4* hs4 = (const float4*)hs;
    for (int c = 0; c < C_; c++) {
        float4 h0 = hs4[c*16 + nq*4 + 0];
        float4 h1 = hs4[c*16 + nq*4 + 1];
        float4 h2 = hs4[c*16 + nq*4 + 2];
        float4 h3 = hs4[c*16 + nq*4 + 3];
        float hv[16] = {h0.x,h0.y,h0.z,h0.w, h1.x,h1.y,h1.z,h1.w,
                        h2.x,h2.y,h2.z,h2.w, h3.x,h3.y,h3.z,h3.w};
        #pragma unroll
        for (int k = 0; k < 6; k++) {
            float wv = W[(size_t)(og + 64*k)*C_ + c];
            #pragma unroll
            for (int j = 0; j < 16; j++) acc[k][j] += wv * hv[j];
        }
    }
    #pragma unroll
    for (int k = 0; k < 6; k++) {
        int o = og + 64*k;
        int which = o >> 7, r = o & 127;
        int head = r >> 5, d = r & 31;
        float* dst = (which == 0) ? g_q : ((which == 1) ? g_k : g_v);
        dst += ((size_t)(bb*NH_ + head) * N_) * HD_ + d;
        float bv = bias[o];
        #pragma unroll
        for (int j = 0; j < 16; j++)
            dst[(size_t)(n0 + nq*16 + j) * HD_] = acc[k][j] + bv;
    }
}

// ================= scores = scale * Q K^T =================
// grid (N/128 jtiles, N/128 itiles, B*NH), block 256 (16x16), 8x8 microtile
__global__ void __launch_bounds__(256) score_kernel() {
    __shared__ float qs[HD_*128];  // [kk][i], 16 KB
    __shared__ float ks[HD_*128];  // [kk][j], 16 KB
    int bh = blockIdx.z;
    int i0 = blockIdx.y * 128, j0 = blockIdx.x * 128;
    const float* qp = g_q + (size_t)bh * N_ * HD_;
    const float* kp = g_k + (size_t)bh * N_ * HD_;
    int tid = threadIdx.x;

    for (int i = tid; i < 1024; i += 256) {
        int row = i >> 3, d4 = i & 7;
        float4 a = *(const float4*)&qp[(size_t)(i0 + row)*HD_ + d4*4];
        float4 b = *(const float4*)&kp[(size_t)(j0 + row)*HD_ + d4*4];
        int c0 = d4 * 4;
        qs[(c0+0)*128 + row] = a.x; qs[(c0+1)*128 + row] = a.y;
        qs[(c0+2)*128 + row] = a.z; qs[(c0+3)*128 + row] = a.w;
        ks[(c0+0)*128 + row] = b.x; ks[(c0+1)*128 + row] = b.y;
        ks[(c0+2)*128 + row] = b.z; ks[(c0+3)*128 + row] = b.w;
    }
    __syncthreads();

    int tx = tid & 15, ty = tid >> 4;
    const float4* qs4 = (const float4*)qs;   // [kk][32 float4]
    const float4* ks4 = (const float4*)ks;
    float acc[8][8];
    #pragma unroll
    for (int r = 0; r < 8; r++)
        #pragma unroll
        for (int c = 0; c < 8; c++) acc[r][c] = 0.f;

    #pragma unroll
    for (int kk = 0; kk < HD_; kk++) {
        float4 aL = qs4[kk*32 + ty];
        float4 aH = qs4[kk*32 + 16 + ty];
        float4 bL = ks4[kk*32 + tx];
        float4 bH = ks4[kk*32 + 16 + tx];
        float av[8] = {aL.x,aL.y,aL.z,aL.w, aH.x,aH.y,aH.z,aH.w};
        float bv[8] = {bL.x,bL.y,bL.z,bL.w, bH.x,bH.y,bH.z,bH.w};
        #pragma unroll
        for (int r = 0; r < 8; r++)
            #pragma unroll
            for (int c = 0; c < 8; c++)
                acc[r][c] += av[r] * bv[c];
    }

    float* sp = g_scores + (size_t)bh * N_ * N_;
    #pragma unroll
    for (int r = 0; r < 8; r++) {
        int i = i0 + ((r < 4) ? (ty*4 + r) : (64 + ty*4 + (r - 4)));
        #pragma unroll
        for (int half = 0; half < 2; half++) {
            int j = j0 + half*64 + tx*4;
            float4 o;
            o.x = acc[r][half*4+0] * SCALE_;
            o.y = acc[r][half*4+1] * SCALE_;
            o.z = acc[r][half*4+2] * SCALE_;
            o.w = acc[r][half*4+3] * SCALE_;
            *(float4*)&sp[(size_t)i*N_ + j] = o;
        }
    }
}

// ================= top-256 select + softmax AV =================
// grid (N, B*NH), block 256 (8 warps). One query row per CTA.
__global__ void __launch_bounds__(256) select_kernel() {
    __shared__ float sv[N_];          // 16 KB: this row's scores
    __shared__ unsigned hist[256];
    __shared__ unsigned ctrl[4];
    __shared__ float redm[8];
    __shared__ float racc[8*HD_];
    __shared__ float rws[8];

    int n = blockIdx.x, bh = blockIdx.y;
    const float* sp = g_scores + (size_t)bh*N_*N_ + (size_t)n*N_;
    const float* vp = g_v + (size_t)bh*N_*HD_;
    int tid = threadIdx.x;
    int lane = tid & 31, w = tid >> 5;

    // load row + row max
    float lmax = -CUDART_INF_F;
    const float4* sp4 = (const float4*)sp;
    float4* sv4 = (float4*)sv;
    for (int i = tid; i < N_/4; i += 256) {
        float4 v = sp4[i];
        sv4[i] = v;
        lmax = fmaxf(fmaxf(lmax, v.x), fmaxf(fmaxf(v.y, v.z), v.w));
    }
    #pragma unroll
    for (int o = 16; o; o >>= 1) lmax = fmaxf(lmax, __shfl_xor_sync(0xffffffffu, lmax, o));
    if (lane == 0) redm[w] = lmax;
    __syncthreads();
    float m = redm[0];
    #pragma unroll
    for (int q = 1; q < 8; q++) m = fmaxf(m, redm[q]);

    // 4-pass MSB radix select for the K-th largest (exact 32-bit value)
    unsigned prefix = 0, prefmask = 0;
    int kth = TK_;
    for (int pass = 0; pass < 4; pass++) {
        int shift = 24 - pass*8;
        hist[tid] = 0;
        __syncthreads();
        for (int i = tid; i < N_; i += 256) {
            unsigned u = ordf(sv[i]);
            bool ok = ((u & prefmask) == prefix);
            int bin = ok ? (int)((u >> shift) & 0xFF) : (256 + lane);
            unsigned mm = __match_any_sync(0xffffffffu, bin);  // warp-aggregate
            if (ok && lane == (__ffs(mm) - 1))
                atomicAdd(&hist[bin], (unsigned)__popc(mm));
        }
        __syncthreads();
        if (tid == 0) {
            int cum = 0, sel = 0;
            for (int b2 = 255; b2 >= 0; b2--) {
                int c = (int)hist[b2];
                if (cum + c >= kth) { sel = b2; break; }
                cum += c;
            }
            ctrl[0] = prefix | ((unsigned)sel << shift);
            ctrl[1] = prefmask | (0xFFu << shift);
            ctrl[2] = (unsigned)(kth - cum);
            ctrl[3] = hist[sel];
        }
        __syncthreads();
        prefix = ctrl[0]; prefmask = ctrl[1]; kth = (int)ctrl[2];
    }
    unsigned ut = prefix;            // exact K-th largest (orderable bits)
    int cnt_eq = (int)ctrl[3];       // elements equal to threshold
    if (cnt_eq > kth) {              // tie at boundary (rare): keep lowest-index ties
        if (tid == 0) {
            int budget = kth;
            for (int j = 0; j < N_; j++) {
                if (ordf(sv[j]) == ut) {
                    if (budget > 0) budget--;
                    else sv[j] = -CUDART_INF_F;
                }
            }
        }
        __syncthreads();
    }

    // softmax-weighted V gather.  lane = head-dim d; each warp scans 512 j's.
    float acc = 0.f, wsum = 0.f;
    int j0 = w * 512;
    #pragma unroll 4
    for (int j = j0; j < j0 + 512; j++) {
        float s = sv[j];                       // smem broadcast, warp-uniform
        if (ordf(s) >= ut) {
            float wt = __expf(s - m);
            acc  += wt * vp[(size_t)j*HD_ + lane];  // coalesced 128B row
            wsum += wt;
        }
    }
    racc[w*HD_ + lane] = acc;
    if (lane == 0) rws[w] = wsum;
    __syncthreads();
    if (w == 0) {
        float a = 0.f, ws = 0.f;
        #pragma unroll
        for (int q = 0; q < 8; q++) { a += racc[q*HD_ + lane]; ws += rws[q]; }
        int head = bh & 3, bb = bh >> 2;
        g_att[((size_t)(bb*C_ + head*HD_ + lane)) * N_ + n] = a / ws;
    }
}

// ================= proj + residual =================
// grid (N/64, B), block 256
__global__ void __launch_bounds__(256) proj_kernel(const float* __restrict__ x,
                                                   const float* __restrict__ W,
                                                   const float* __restrict__ bias,
                                                   float* __restrict__ out) {
    __shared__ float as_[C_*64];
    int n0 = blockIdx.x * 64, bb = blockIdx.y;
    int tid = threadIdx.x;
    const float* ap = g_att + (size_t)bb * C_ * N_;
    for (int i = tid; i < C_*64; i += 256) {
        int c = i >> 6, nl = i & 63;
        as_[i] = ap[(size_t)c*N_ + n0 + nl];
    }
    __syncthreads();

    int nq = tid & 3, og = tid >> 2;
    float acc[2][16];
    #pragma unroll
    for (int k = 0; k < 2; k++)
        #pragma unroll
        for (int j = 0; j < 16; j++) acc[k][j] = 0.f;

    const float4* as4 = (const float4*)as_;
    for (int c = 0; c < C_; c++) {
        float4 h0 = as4[c*16 + nq*4 + 0];
        float4 h1 = as4[c*16 + nq*4 + 1];
        float4 h2 = as4[c*16 + nq*4 + 2];
        float4 h3 = as4[c*16 + nq*4 + 3];
        float hv[16] = {h0.x,h0.y,h0.z,h0.w, h1.x,h1.y,h1.z,h1.w,
                        h2.x,h2.y,h2.z,h2.w, h3.x,h3.y,h3.z,h3.w};
        #pragma unroll
        for (int k = 0; k < 2; k++) {
            float wv = W[(size_t)(og + 64*k)*C_ + c];
            #pragma unroll
            for (int j = 0; j < 16; j++) acc[k][j] += wv * hv[j];
        }
    }
    #pragma unroll
    for (int k = 0; k < 2; k++) {
        int o = og + 64*k;
        float bv = bias[o];
        size_t base = ((size_t)bb*C_ + o)*N_ + n0 + nq*16;
        #pragma unroll
        for (int j4 = 0; j4 < 4; j4++) {
            float4 xi = *(const float4*)&x[base + j4*4];
            float4 r;
            r.x = acc[k][j4*4+0] + bv + xi.x;
            r.y = acc[k][j4*4+1] + bv + xi.y;
            r.z = acc[k][j4*4+2] + bv + xi.z;
            r.w = acc[k][j4*4+3] + bv + xi.w;
            *(float4*)&out[base + j4*4] = r;
        }
    }
}

// ================= launch =================
extern "C" void kernel_launch(void* const* d_in, const int* in_sizes, int n_in,
                              void* d_out, int out_size) {
    const float* x      = (const float*)d_in[0];
    const float* gn_w   = (const float*)d_in[1];
    const float* gn_b   = (const float*)d_in[2];
    const float* qkv_w  = (const float*)d_in[3];
    const float* qkv_b  = (const float*)d_in[4];
    const float* proj_w = (const float*)d_in[5];
    const float* proj_b = (const float*)d_in[6];
    float* out = (float*)d_out;

    gn_kernel    <<<B_*GR_, 256>>>(x, gn_w, gn_b);
    qkv_kernel   <<<dim3(N_/64, B_), 256>>>(qkv_w, qkv_b);
    score_kernel <<<dim3(N_/128, N_/128, B_*NH_), 256>>>();
    select_kernel<<<dim3(N_, B_*NH_), 256>>>();
    proj_kernel  <<<dim3(N_/64, B_), 256>>>(x, proj_w, proj_b, out);
}

// round 5
// speedup vs baseline: 2.4635x; 2.4635x over previous
#include <cuda_runtime.h>
#include <math_constants.h>
#include <stdint.h>

#define B_    2
#define C_    128
#define N_    4096
#define GR_   32
#define CPG_  4
#define NH_   4
#define HD_   32
#define TK_   256
#define EPS_  1e-5f
#define SCALE_ 0.17677669529663689f   // 32^-0.5

// -------- scratch (device globals; no allocation allowed) --------
static __device__ float g_h[B_*C_*N_];                 // 4 MB groupnorm output
static __device__ float g_q[B_*NH_*N_*HD_];            // 4 MB  (b,h,n,d)
static __device__ float g_k[B_*NH_*N_*HD_];            // 4 MB
static __device__ float g_v[B_*NH_*N_*HD_];            // 4 MB
static __device__ float g_att[B_*C_*N_];               // 4 MB  (b,c,n)
static __device__ float g_scores[(size_t)B_*NH_*N_*N_];// 512 MB (bh,n,j)

__device__ __forceinline__ unsigned ordf(float f) {
    unsigned u = __float_as_uint(f);
    return (u & 0x80000000u) ? ~u : (u | 0x80000000u);   // monotonic float->uint
}

// ================= GroupNorm =================
__global__ void __launch_bounds__(256) gn_kernel(const float* __restrict__ x,
                                                 const float* __restrict__ w,
                                                 const float* __restrict__ b) {
    int bg = blockIdx.x;
    int bb = bg / GR_, g = bg % GR_;
    const float* xp = x + ((size_t)bb*C_ + g*CPG_) * N_;
    float*       hp = g_h + ((size_t)bb*C_ + g*CPG_) * N_;
    int tid = threadIdx.x;

    float s = 0.f, s2 = 0.f;
    for (int i = tid; i < CPG_*N_; i += 256) {
        float v = xp[i];
        s += v; s2 += v*v;
    }
    __shared__ float rs[8], rs2[8];
    __shared__ float mu_s, rstd_s;
    #pragma unroll
    for (int o = 16; o; o >>= 1) {
        s  += __shfl_down_sync(0xffffffffu, s,  o);
        s2 += __shfl_down_sync(0xffffffffu, s2, o);
    }
    if ((tid & 31) == 0) { rs[tid>>5] = s; rs2[tid>>5] = s2; }
    __syncthreads();
    if (tid == 0) {
        float t = 0.f, t2 = 0.f;
        #pragma unroll
        for (int i = 0; i < 8; i++) { t += rs[i]; t2 += rs2[i]; }
        float inv = 1.f / (float)(CPG_*N_);
        float mu = t * inv;
        float var = t2 * inv - mu*mu;
        mu_s = mu;
        rstd_s = rsqrtf(var + EPS_);
    }
    __syncthreads();
    float mu = mu_s, rstd = rstd_s;
    for (int i = tid; i < CPG_*N_; i += 256) {
        int c = g*CPG_ + i / N_;
        hp[i] = (xp[i] - mu) * rstd * w[c] + b[c];
    }
}

// ================= QKV GEMM =================
__global__ void __launch_bounds__(256) qkv_kernel(const float* __restrict__ W,
                                                  const float* __restrict__ bias) {
    __shared__ float hs[C_*64];
    int n0 = blockIdx.x * 64;
    int bb = blockIdx.y;
    int tid = threadIdx.x;
    const float* hp = g_h + (size_t)bb * C_ * N_;
    for (int i = tid; i < C_*64; i += 256) {
        int c = i >> 6, nl = i & 63;
        hs[i] = hp[(size_t)c*N_ + n0 + nl];
    }
    __syncthreads();

    int nq = tid & 3;
    int og = tid >> 2;
    float acc[6][16];
    #pragma unroll
    for (int k = 0; k < 6; k++)
        #pragma unroll
        for (int j = 0; j < 16; j++) acc[k][j] = 0.f;

    const float4* hs4 = (const float4*)hs;
    for (int c = 0; c < C_; c++) {
        float4 h0 = hs4[c*16 + nq*4 + 0];
        float4 h1 = hs4[c*16 + nq*4 + 1];
        float4 h2 = hs4[c*16 + nq*4 + 2];
        float4 h3 = hs4[c*16 + nq*4 + 3];
        float hv[16] = {h0.x,h0.y,h0.z,h0.w, h1.x,h1.y,h1.z,h1.w,
                        h2.x,h2.y,h2.z,h2.w, h3.x,h3.y,h3.z,h3.w};
        #pragma unroll
        for (int k = 0; k < 6; k++) {
            float wv = W[(size_t)(og + 64*k)*C_ + c];
            #pragma unroll
            for (int j = 0; j < 16; j++) acc[k][j] += wv * hv[j];
        }
    }
    #pragma unroll
    for (int k = 0; k < 6; k++) {
        int o = og + 64*k;
        int which = o >> 7, r = o & 127;
        int head = r >> 5, d = r & 31;
        float* dst = (which == 0) ? g_q : ((which == 1) ? g_k : g_v);
        dst += ((size_t)(bb*NH_ + head) * N_) * HD_ + d;
        float bv = bias[o];
        #pragma unroll
        for (int j = 0; j < 16; j++)
            dst[(size_t)(n0 + nq*16 + j) * HD_] = acc[k][j] + bv;
    }
}

// ================= scores = scale * Q K^T =================
__global__ void __launch_bounds__(256) score_kernel() {
    __shared__ float qs[HD_*128];
    __shared__ float ks[HD_*128];
    int bh = blockIdx.z;
    int i0 = blockIdx.y * 128, j0 = blockIdx.x * 128;
    const float* qp = g_q + (size_t)bh * N_ * HD_;
    const float* kp = g_k + (size_t)bh * N_ * HD_;
    int tid = threadIdx.x;

    for (int i = tid; i < 1024; i += 256) {
        int row = i >> 3, d4 = i & 7;
        float4 a = *(const float4*)&qp[(size_t)(i0 + row)*HD_ + d4*4];
        float4 b = *(const float4*)&kp[(size_t)(j0 + row)*HD_ + d4*4];
        int c0 = d4 * 4;
        qs[(c0+0)*128 + row] = a.x; qs[(c0+1)*128 + row] = a.y;
        qs[(c0+2)*128 + row] = a.z; qs[(c0+3)*128 + row] = a.w;
        ks[(c0+0)*128 + row] = b.x; ks[(c0+1)*128 + row] = b.y;
        ks[(c0+2)*128 + row] = b.z; ks[(c0+3)*128 + row] = b.w;
    }
    __syncthreads();

    int tx = tid & 15, ty = tid >> 4;
    const float4* qs4 = (const float4*)qs;
    const float4* ks4 = (const float4*)ks;
    float acc[8][8];
    #pragma unroll
    for (int r = 0; r < 8; r++)
        #pragma unroll
        for (int c = 0; c < 8; c++) acc[r][c] = 0.f;

    #pragma unroll
    for (int kk = 0; kk < HD_; kk++) {
        float4 aL = qs4[kk*32 + ty];
        float4 aH = qs4[kk*32 + 16 + ty];
        float4 bL = ks4[kk*32 + tx];
        float4 bH = ks4[kk*32 + 16 + tx];
        float av[8] = {aL.x,aL.y,aL.z,aL.w, aH.x,aH.y,aH.z,aH.w};
        float bv[8] = {bL.x,bL.y,bL.z,bL.w, bH.x,bH.y,bH.z,bH.w};
        #pragma unroll
        for (int r = 0; r < 8; r++)
            #pragma unroll
            for (int c = 0; c < 8; c++)
                acc[r][c] += av[r] * bv[c];
    }

    float* sp = g_scores + (size_t)bh * N_ * N_;
    #pragma unroll
    for (int r = 0; r < 8; r++) {
        int i = i0 + ((r < 4) ? (ty*4 + r) : (64 + ty*4 + (r - 4)));
        #pragma unroll
        for (int half = 0; half < 2; half++) {
            int j = j0 + half*64 + tx*4;
            float4 o;
            o.x = acc[r][half*4+0] * SCALE_;
            o.y = acc[r][half*4+1] * SCALE_;
            o.z = acc[r][half*4+2] * SCALE_;
            o.w = acc[r][half*4+3] * SCALE_;
            *(float4*)&sp[(size_t)i*N_ + j] = o;
        }
    }
}

// ---- parallel bin selection via shuffle suffix-sum (replaces serial scan) ----
__device__ __forceinline__ void bin_select(unsigned* hist, unsigned* wtt,
                                           unsigned* ctrl, int tid, int lane,
                                           int w, int kth, unsigned prefix,
                                           int shift) {
    unsigned c = hist[tid];
    unsigned s = c;
    #pragma unroll
    for (int off = 1; off < 32; off <<= 1) {
        unsigned o = __shfl_down_sync(0xffffffffu, s, off);
        if (lane + off < 32) s += o;
    }
    if (lane == 0) wtt[w] = s;   // warp totals
    __syncthreads();
    unsigned add = 0;
    #pragma unroll
    for (int q = 0; q < 8; q++) if (q > w) add += wtt[q];
    unsigned Sincl = s + add;          // elems in bins >= tid
    unsigned Sexcl = Sincl - c;        // elems in bins >  tid
    if (Sexcl < (unsigned)kth && (unsigned)kth <= Sincl) {
        ctrl[0] = prefix | ((unsigned)tid << shift);
        ctrl[2] = (unsigned)kth - Sexcl;
        ctrl[3] = c;
    }
    __syncthreads();
}

// ================= top-256 select + softmax AV =================
// grid (N, B*NH), block 256 (8 warps). One query row per CTA.
__global__ void __launch_bounds__(256) select_kernel() {
    __shared__ float sv[N_];          // 16 KB row scores
    __shared__ unsigned candv[N_];    // 16 KB candidate ordf values
    __shared__ unsigned hist[256];
    __shared__ unsigned wtt[8];
    __shared__ unsigned ctrl[4];
    __shared__ unsigned scnt[2];
    __shared__ float redm[8];
    __shared__ int   idxs[TK_];
    __shared__ float wts[TK_];
    __shared__ float racc[8*HD_];
    __shared__ float rws[8];

    int n = blockIdx.x, bh = blockIdx.y;
    const float* sp = g_scores + (size_t)bh*N_*N_ + (size_t)n*N_;
    const float* vp = g_v + (size_t)bh*N_*HD_;
    int tid = threadIdx.x;
    int lane = tid & 31, w = tid >> 5;

    hist[tid] = 0;
    if (tid < 2) scnt[tid] = 0;
    __syncthreads();

    // ---- load row + row max + pass-0 histogram (top byte), fused ----
    float lmax = -CUDART_INF_F;
    const float4* sp4 = (const float4*)sp;
    float4* sv4 = (float4*)sv;
    #pragma unroll
    for (int it = 0; it < 4; it++) {
        int i4 = tid + it*256;
        float4 v = sp4[i4];
        sv4[i4] = v;
        lmax = fmaxf(fmaxf(lmax, v.x), fmaxf(fmaxf(v.y, v.z), v.w));
        float comp[4] = {v.x, v.y, v.z, v.w};
        #pragma unroll
        for (int c = 0; c < 4; c++) {
            int bin = (int)(ordf(comp[c]) >> 24);
            unsigned mm = __match_any_sync(0xffffffffu, bin);
            if (lane == (__ffs(mm) - 1))
                atomicAdd(&hist[bin], (unsigned)__popc(mm));
        }
    }
    #pragma unroll
    for (int o = 16; o; o >>= 1) lmax = fmaxf(lmax, __shfl_xor_sync(0xffffffffu, lmax, o));
    if (lane == 0) redm[w] = lmax;
    __syncthreads();
    float m = redm[0];
    #pragma unroll
    for (int q = 1; q < 8; q++) m = fmaxf(m, redm[q]);

    // ---- pass-0 bin selection ----
    bin_select(hist, wtt, ctrl, tid, lane, w, TK_, 0u, 24);
    unsigned prefix = ctrl[0];
    int kth = (int)ctrl[2];

    // ---- compact candidates (elements whose top byte matches) ----
    #pragma unroll
    for (int it = 0; it < 16; it++) {
        int i = tid + it*256;
        unsigned u = ordf(sv[i]);
        bool pred = ((u & 0xFF000000u) == prefix);
        unsigned bal = __ballot_sync(0xffffffffu, pred);
        int base = 0;
        if (lane == 0 && bal) base = (int)atomicAdd(&scnt[0], (unsigned)__popc(bal));
        base = __shfl_sync(0xffffffffu, base, 0);
        if (pred) {
            int pos = base + __popc(bal & ((1u << lane) - 1u));
            candv[pos] = u;
        }
    }
    __syncthreads();
    int nc = (int)scnt[0];
    unsigned prefmask = 0xFF000000u;

    // ---- passes 1..3 over candidates only ----
    for (int pass = 1; pass < 4; pass++) {
        int shift = 24 - pass*8;
        hist[tid] = 0;
        __syncthreads();
        int padded = (nc + 255) & ~255;
        for (int i = tid; i < padded; i += 256) {
            unsigned u = (i < nc) ? candv[i] : 0u;
            bool ok = (i < nc) && ((u & prefmask) == prefix);
            int bin = ok ? (int)((u >> shift) & 0xFF) : 256 + lane;
            unsigned mm = __match_any_sync(0xffffffffu, bin);
            if (ok && lane == (__ffs(mm) - 1))
                atomicAdd(&hist[bin], (unsigned)__popc(mm));
        }
        __syncthreads();
        bin_select(hist, wtt, ctrl, tid, lane, w, kth, prefix, shift);
        prefix = ctrl[0];
        kth = (int)ctrl[2];
        prefmask |= (0xFFu << shift);
    }
    unsigned ut = prefix;            // exact K-th largest (orderable bits)
    int cnt_eq = (int)ctrl[3];
    if (cnt_eq > kth) {              // tie at boundary (rare): keep lowest-index ties
        if (tid == 0) {
            int budget = kth;
            for (int j = 0; j < N_; j++) {
                if (ordf(sv[j]) == ut) {
                    if (budget > 0) budget--;
                    else sv[j] = -CUDART_INF_F;
                }
            }
        }
        __syncthreads();
    }

    // ---- compact the 256 selected (index + softmax weight) ----
    #pragma unroll
    for (int it = 0; it < 16; it++) {
        int i = tid + it*256;
        float s = sv[i];
        bool pred = (ordf(s) >= ut);
        unsigned bal = __ballot_sync(0xffffffffu, pred);
        int base = 0;
        if (lane == 0 && bal) base = (int)atomicAdd(&scnt[1], (unsigned)__popc(bal));
        base = __shfl_sync(0xffffffffu, base, 0);
        if (pred) {
            int pos = base + __popc(bal & ((1u << lane) - 1u));
            idxs[pos] = i;
            wts[pos]  = __expf(s - m);
        }
    }
    __syncthreads();

    // ---- AV over 256 selected only: 32 entries per warp, lane = head dim ----
    float acc = 0.f, wsum = 0.f;
    int e0 = w * 32;
    #pragma unroll 4
    for (int e = e0; e < e0 + 32; e++) {
        int j = idxs[e];
        float wt = wts[e];
        acc  += wt * vp[(size_t)j*HD_ + lane];
        wsum += wt;
    }
    racc[w*HD_ + lane] = acc;
    if (lane == 0) rws[w] = wsum;
    __syncthreads();
    if (w == 0) {
        float a = 0.f, ws = 0.f;
        #pragma unroll
        for (int q = 0; q < 8; q++) { a += racc[q*HD_ + lane]; ws += rws[q]; }
        int head = bh & 3, bb = bh >> 2;
        g_att[((size_t)(bb*C_ + head*HD_ + lane)) * N_ + n] = a / ws;
    }
}

// ================= proj + residual =================
__global__ void __launch_bounds__(256) proj_kernel(const float* __restrict__ x,
                                                   const float* __restrict__ W,
                                                   const float* __restrict__ bias,
                                                   float* __restrict__ out) {
    __shared__ float as_[C_*64];
    int n0 = blockIdx.x * 64, bb = blockIdx.y;
    int tid = threadIdx.x;
    const float* ap = g_att + (size_t)bb * C_ * N_;
    for (int i = tid; i < C_*64; i += 256) {
        int c = i >> 6, nl = i & 63;
        as_[i] = ap[(size_t)c*N_ + n0 + nl];
    }
    __syncthreads();

    int nq = tid & 3, og = tid >> 2;
    float acc[2][16];
    #pragma unroll
    for (int k = 0; k < 2; k++)
        #pragma unroll
        for (int j = 0; j < 16; j++) acc[k][j] = 0.f;

    const float4* as4 = (const float4*)as_;
    for (int c = 0; c < C_; c++) {
        float4 h0 = as4[c*16 + nq*4 + 0];
        float4 h1 = as4[c*16 + nq*4 + 1];
        float4 h2 = as4[c*16 + nq*4 + 2];
        float4 h3 = as4[c*16 + nq*4 + 3];
        float hv[16] = {h0.x,h0.y,h0.z,h0.w, h1.x,h1.y,h1.z,h1.w,
                        h2.x,h2.y,h2.z,h2.w, h3.x,h3.y,h3.z,h3.w};
        #pragma unroll
        for (int k = 0; k < 2; k++) {
            float wv = W[(size_t)(og + 64*k)*C_ + c];
            #pragma unroll
            for (int j = 0; j < 16; j++) acc[k][j] += wv * hv[j];
        }
    }
    #pragma unroll
    for (int k = 0; k < 2; k++) {
        int o = og + 64*k;
        float bv = bias[o];
        size_t base = ((size_t)bb*C_ + o)*N_ + n0 + nq*16;
        #pragma unroll
        for (int j4 = 0; j4 < 4; j4++) {
            float4 xi = *(const float4*)&x[base + j4*4];
            float4 r;
            r.x = acc[k][j4*4+0] + bv + xi.x;
            r.y = acc[k][j4*4+1] + bv + xi.y;
            r.z = acc[k][j4*4+2] + bv + xi.z;
            r.w = acc[k][j4*4+3] + bv + xi.w;
            *(float4*)&out[base + j4*4] = r;
        }
    }
}

// ================= launch =================
extern "C" void kernel_launch(void* const* d_in, const int* in_sizes, int n_in,
                              void* d_out, int out_size) {
    const float* x      = (const float*)d_in[0];
    const float* gn_w   = (const float*)d_in[1];
    const float* gn_b   = (const float*)d_in[2];
    const float* qkv_w  = (const float*)d_in[3];
    const float* qkv_b  = (const float*)d_in[4];
    const float* proj_w = (const float*)d_in[5];
    const float* proj_b = (const float*)d_in[6];
    float* out = (float*)d_out;

    gn_kernel    <<<B_*GR_, 256>>>(x, gn_w, gn_b);
    qkv_kernel   <<<dim3(N_/64, B_), 256>>>(qkv_w, qkv_b);
    score_kernel <<<dim3(N_/128, N_/128, B_*NH_), 256>>>();
    select_kernel<<<dim3(N_, B_*NH_), 256>>>();
    proj_kernel  <<<dim3(N_/64, B_), 256>>>(x, proj_w, proj_b, out);
}

// round 6
// speedup vs baseline: 2.7256x; 1.1064x over previous
#include <cuda_runtime.h>
#include <math_constants.h>
#include <stdint.h>

#define B_    2
#define C_    128
#define N_    4096
#define GR_   32
#define CPG_  4
#define NH_   4
#define HD_   32
#define TK_   256
#define EPS_  1e-5f
#define SCALE_ 0.17677669529663689f   // 32^-0.5

// -------- scratch (device globals; no allocation allowed) --------
static __device__ float g_h[B_*C_*N_];
static __device__ float g_q[B_*NH_*N_*HD_];
static __device__ float g_k[B_*NH_*N_*HD_];
static __device__ float g_v[B_*NH_*N_*HD_];
static __device__ float g_att[B_*C_*N_];
static __device__ float g_scores[(size_t)B_*NH_*N_*N_];  // 512 MB

__device__ __forceinline__ unsigned ordf(float f) {
    unsigned u = __float_as_uint(f);
    return (u & 0x80000000u) ? ~u : (u | 0x80000000u);
}
__device__ __forceinline__ float iordf(unsigned u) {
    return __uint_as_float((u & 0x80000000u) ? (u ^ 0x80000000u) : ~u);
}

// ================= GroupNorm =================
__global__ void __launch_bounds__(256) gn_kernel(const float* __restrict__ x,
                                                 const float* __restrict__ w,
                                                 const float* __restrict__ b) {
    int bg = blockIdx.x;
    int bb = bg / GR_, g = bg % GR_;
    const float* xp = x + ((size_t)bb*C_ + g*CPG_) * N_;
    float*       hp = g_h + ((size_t)bb*C_ + g*CPG_) * N_;
    int tid = threadIdx.x;

    float s = 0.f, s2 = 0.f;
    for (int i = tid; i < CPG_*N_; i += 256) {
        float v = xp[i];
        s += v; s2 += v*v;
    }
    __shared__ float rs[8], rs2[8];
    __shared__ float mu_s, rstd_s;
    #pragma unroll
    for (int o = 16; o; o >>= 1) {
        s  += __shfl_down_sync(0xffffffffu, s,  o);
        s2 += __shfl_down_sync(0xffffffffu, s2, o);
    }
    if ((tid & 31) == 0) { rs[tid>>5] = s; rs2[tid>>5] = s2; }
    __syncthreads();
    if (tid == 0) {
        float t = 0.f, t2 = 0.f;
        #pragma unroll
        for (int i = 0; i < 8; i++) { t += rs[i]; t2 += rs2[i]; }
        float inv = 1.f / (float)(CPG_*N_);
        float mu = t * inv;
        float var = t2 * inv - mu*mu;
        mu_s = mu;
        rstd_s = rsqrtf(var + EPS_);
    }
    __syncthreads();
    float mu = mu_s, rstd = rstd_s;
    for (int i = tid; i < CPG_*N_; i += 256) {
        int c = g*CPG_ + i / N_;
        hp[i] = (xp[i] - mu) * rstd * w[c] + b[c];
    }
}

// ================= QKV GEMM =================
__global__ void __launch_bounds__(256) qkv_kernel(const float* __restrict__ W,
                                                  const float* __restrict__ bias) {
    __shared__ float hs[C_*64];
    int n0 = blockIdx.x * 64;
    int bb = blockIdx.y;
    int tid = threadIdx.x;
    const float* hp = g_h + (size_t)bb * C_ * N_;
    for (int i = tid; i < C_*64; i += 256) {
        int c = i >> 6, nl = i & 63;
        hs[i] = hp[(size_t)c*N_ + n0 + nl];
    }
    __syncthreads();

    int nq = tid & 3;
    int og = tid >> 2;
    float acc[6][16];
    #pragma unroll
    for (int k = 0; k < 6; k++)
        #pragma unroll
        for (int j = 0; j < 16; j++) acc[k][j] = 0.f;

    const float4* hs4 = (const float4*)hs;
    for (int c = 0; c < C_; c++) {
        float4 h0 = hs4[c*16 + nq*4 + 0];
        float4 h1 = hs4[c*16 + nq*4 + 1];
        float4 h2 = hs4[c*16 + nq*4 + 2];
        float4 h3 = hs4[c*16 + nq*4 + 3];
        float hv[16] = {h0.x,h0.y,h0.z,h0.w, h1.x,h1.y,h1.z,h1.w,
                        h2.x,h2.y,h2.z,h2.w, h3.x,h3.y,h3.z,h3.w};
        #pragma unroll
        for (int k = 0; k < 6; k++) {
            float wv = W[(size_t)(og + 64*k)*C_ + c];
            #pragma unroll
            for (int j = 0; j < 16; j++) acc[k][j] += wv * hv[j];
        }
    }
    #pragma unroll
    for (int k = 0; k < 6; k++) {
        int o = og + 64*k;
        int which = o >> 7, r = o & 127;
        int head = r >> 5, d = r & 31;
        float* dst = (which == 0) ? g_q : ((which == 1) ? g_k : g_v);
        dst += ((size_t)(bb*NH_ + head) * N_) * HD_ + d;
        float bv = bias[o];
        #pragma unroll
        for (int j = 0; j < 16; j++)
            dst[(size_t)(n0 + nq*16 + j) * HD_] = acc[k][j] + bv;
    }
}

// ================= scores = scale * Q K^T =================
__global__ void __launch_bounds__(256) score_kernel() {
    __shared__ float qs[HD_*128];
    __shared__ float ks[HD_*128];
    int bh = blockIdx.z;
    int i0 = blockIdx.y * 128, j0 = blockIdx.x * 128;
    const float* qp = g_q + (size_t)bh * N_ * HD_;
    const float* kp = g_k + (size_t)bh * N_ * HD_;
    int tid = threadIdx.x;

    for (int i = tid; i < 1024; i += 256) {
        int row = i >> 3, d4 = i & 7;
        float4 a = *(const float4*)&qp[(size_t)(i0 + row)*HD_ + d4*4];
        float4 b = *(const float4*)&kp[(size_t)(j0 + row)*HD_ + d4*4];
        int c0 = d4 * 4;
        qs[(c0+0)*128 + row] = a.x; qs[(c0+1)*128 + row] = a.y;
        qs[(c0+2)*128 + row] = a.z; qs[(c0+3)*128 + row] = a.w;
        ks[(c0+0)*128 + row] = b.x; ks[(c0+1)*128 + row] = b.y;
        ks[(c0+2)*128 + row] = b.z; ks[(c0+3)*128 + row] = b.w;
    }
    __syncthreads();

    int tx = tid & 15, ty = tid >> 4;
    const float4* qs4 = (const float4*)qs;
    const float4* ks4 = (const float4*)ks;
    float acc[8][8];
    #pragma unroll
    for (int r = 0; r < 8; r++)
        #pragma unroll
        for (int c = 0; c < 8; c++) acc[r][c] = 0.f;

    #pragma unroll
    for (int kk = 0; kk < HD_; kk++) {
        float4 aL = qs4[kk*32 + ty];
        float4 aH = qs4[kk*32 + 16 + ty];
        float4 bL = ks4[kk*32 + tx];
        float4 bH = ks4[kk*32 + 16 + tx];
        float av[8] = {aL.x,aL.y,aL.z,aL.w, aH.x,aH.y,aH.z,aH.w};
        float bv[8] = {bL.x,bL.y,bL.z,bL.w, bH.x,bH.y,bH.z,bH.w};
        #pragma unroll
        for (int r = 0; r < 8; r++)
            #pragma unroll
            for (int c = 0; c < 8; c++)
                acc[r][c] += av[r] * bv[c];
    }

    float* sp = g_scores + (size_t)bh * N_ * N_;
    #pragma unroll
    for (int r = 0; r < 8; r++) {
        int i = i0 + ((r < 4) ? (ty*4 + r) : (64 + ty*4 + (r - 4)));
        #pragma unroll
        for (int half = 0; half < 2; half++) {
            int j = j0 + half*64 + tx*4;
            float4 o;
            o.x = acc[r][half*4+0] * SCALE_;
            o.y = acc[r][half*4+1] * SCALE_;
            o.z = acc[r][half*4+2] * SCALE_;
            o.w = acc[r][half*4+3] * SCALE_;
            __stcs((float4*)&sp[(size_t)i*N_ + j], o);   // streaming: don't thrash L2
        }
    }
}

// ================= top-256 select + softmax AV (register-resident) ========
// grid (N, B*NH), block 256 (8 warps). One query row per CTA.
// Scores live in registers (16/thread). 11-bit single-pass histogram selects
// a quarter-binade bin (~50-150 elems); exact k-th found by rank count.
__global__ void __launch_bounds__(256) select_kernel() {
    __shared__ unsigned hist[2048];   // 8 KB, strided layout pos=(bin&7)*256+(bin>>3)
    __shared__ unsigned cand[1024];   // 4 KB candidate ordf values
    __shared__ unsigned wtt[8];
    __shared__ unsigned ctrl[8];
    __shared__ unsigned scnt[4];
    __shared__ float redm[8];
    __shared__ int   idxs[TK_];
    __shared__ float wts[TK_];
    __shared__ int   eqidx[256];
    __shared__ float racc[8*HD_];
    __shared__ float rws[8];

    int n = blockIdx.x, bh = blockIdx.y;
    const float4* sp4 = (const float4*)(g_scores + (size_t)bh*N_*N_ + (size_t)n*N_);
    const float* vp = g_v + (size_t)bh*N_*HD_;
    int tid = threadIdx.x;
    int lane = tid & 31, w = tid >> 5;

    #pragma unroll
    for (int k = 0; k < 8; k++) hist[k*256 + tid] = 0;
    if (tid < 4) scnt[tid] = 0;
    __syncthreads();

    // ---- load row into registers + row max + 11-bit histogram ----
    float4 v[4];
    float lmax = -CUDART_INF_F;
    #pragma unroll
    for (int it = 0; it < 4; it++) {
        v[it] = __ldcs(&sp4[tid + it*256]);
        float comp[4] = {v[it].x, v[it].y, v[it].z, v[it].w};
        #pragma unroll
        for (int c = 0; c < 4; c++) {
            lmax = fmaxf(lmax, comp[c]);
            unsigned bin = ordf(comp[c]) >> 21;             // 0..2047
            unsigned mm = __match_any_sync(0xffffffffu, bin);
            if (lane == (__ffs(mm) - 1)) {
                unsigned pos = ((bin & 7u) << 8) | (bin >> 3);
                atomicAdd(&hist[pos], (unsigned)__popc(mm));
            }
        }
    }
    #pragma unroll
    for (int o = 16; o; o >>= 1) lmax = fmaxf(lmax, __shfl_xor_sync(0xffffffffu, lmax, o));
    if (lane == 0) redm[w] = lmax;
    __syncthreads();
    float m = redm[0];
    #pragma unroll
    for (int q = 1; q < 8; q++) m = fmaxf(m, redm[q]);

    // ---- 2048-bin selection: thread tid owns bins tid*8+k at hist[k*256+tid] ----
    unsigned own[8]; unsigned tot = 0;
    #pragma unroll
    for (int k = 0; k < 8; k++) { own[k] = hist[k*256 + tid]; tot += own[k]; }
    unsigned s = tot;
    #pragma unroll
    for (int off = 1; off < 32; off <<= 1) {
        unsigned o = __shfl_down_sync(0xffffffffu, s, off);
        if (lane + off < 32) s += o;
    }
    if (lane == 0) wtt[w] = s;
    __syncthreads();
    unsigned add = 0;
    #pragma unroll
    for (int q = 0; q < 8; q++) if (q > w) add += wtt[q];
    unsigned cum = s + add - tot;     // elems in bins strictly above this thread's group
    #pragma unroll
    for (int k = 7; k >= 0; k--) {
        unsigned cn = own[k];
        if (cum < TK_ && TK_ <= cum + cn) {
            ctrl[0] = (unsigned)(tid*8 + k);   // selected 11-bit bin
            ctrl[1] = TK_ - cum;               // k-th within bin
            ctrl[2] = cn;                      // bin count
        }
        cum += cn;
    }
    __syncthreads();
    unsigned selbin = ctrl[0];
    int kth = (int)ctrl[1];
    int bincnt = (int)ctrl[2];

    unsigned ut;       // exact k-th largest (orderable)
    int need, eq;      // how many ==ut to keep; total ==ut

    if (bincnt <= 1024) {
        // ---- fast path: compact bin members, rank-count exact k-th ----
        #pragma unroll
        for (int it = 0; it < 4; it++) {
            float comp[4] = {v[it].x, v[it].y, v[it].z, v[it].w};
            #pragma unroll
            for (int c = 0; c < 4; c++) {
                unsigned u = ordf(comp[c]);
                bool pred = ((u >> 21) == selbin);
                unsigned bal = __ballot_sync(0xffffffffu, pred);
                int base = 0;
                if (lane == 0 && bal) base = (int)atomicAdd(&scnt[0], (unsigned)__popc(bal));
                base = __shfl_sync(0xffffffffu, base, 0);
                if (pred) cand[base + __popc(bal & ((1u << lane) - 1u))] = u;
            }
        }
        __syncthreads();
        for (int i = tid; i < bincnt; i += 256) {
            unsigned ui = cand[i];
            int gt = 0, e = 0;
            for (int j = 0; j < bincnt; j++) {
                unsigned uj = cand[j];
                gt += (uj > ui);
                e  += (uj == ui);
            }
            if (gt < kth && kth <= gt + e) {
                ctrl[3] = ui; ctrl[4] = (unsigned)gt; ctrl[5] = (unsigned)e;
            }
        }
        __syncthreads();
        ut = ctrl[3];
        need = kth - (int)ctrl[4];
        eq = (int)ctrl[5];
    } else {
        // ---- fallback: three more radix passes over register values ----
        unsigned prefix = selbin << 21;
        unsigned pmask = 0xFFE00000u;
        int kth2 = kth;
        int shifts[3] = {13, 5, 0};
        unsigned bmasks[3] = {0xFFu, 0xFFu, 0x1Fu};
        unsigned lastcnt = 0;
        for (int p = 0; p < 3; p++) {
            int sh = shifts[p];
            unsigned bm = bmasks[p];
            hist[tid] = 0;
            __syncthreads();
            #pragma unroll
            for (int it = 0; it < 4; it++) {
                float comp[4] = {v[it].x, v[it].y, v[it].z, v[it].w};
                #pragma unroll
                for (int c = 0; c < 4; c++) {
                    unsigned u = ordf(comp[c]);
                    bool ok = ((u & pmask) == prefix);
                    unsigned bin = ok ? ((u >> sh) & bm) : (0x800u + lane);
                    unsigned mm = __match_any_sync(0xffffffffu, bin);
                    if (ok && lane == (__ffs(mm) - 1))
                        atomicAdd(&hist[bin], (unsigned)__popc(mm));
                }
            }
            __syncthreads();
            {   // 256-bin suffix selection
                unsigned c2 = hist[tid];
                unsigned s2 = c2;
                #pragma unroll
                for (int off = 1; off < 32; off <<= 1) {
                    unsigned o = __shfl_down_sync(0xffffffffu, s2, off);
                    if (lane + off < 32) s2 += o;
                }
                if (lane == 0) wtt[w] = s2;
                __syncthreads();
                unsigned ad = 0;
                #pragma unroll
                for (int q = 0; q < 8; q++) if (q > w) ad += wtt[q];
                unsigned Sincl = s2 + ad, Sexcl = Sincl - c2;
                if (Sexcl < (unsigned)kth2 && (unsigned)kth2 <= Sincl) {
                    ctrl[0] = prefix | ((unsigned)tid << sh);
                    ctrl[1] = (unsigned)kth2 - Sexcl;
                    ctrl[2] = c2;
                }
                __syncthreads();
            }
            prefix = ctrl[0];
            kth2 = (int)ctrl[1];
            lastcnt = ctrl[2];
            pmask |= (bm << sh);
        }
        ut = prefix;
        need = kth2;
        eq = (int)lastcnt;
    }

    // ---- compact selected entries ----
    if (eq == need) {
        #pragma unroll
        for (int it = 0; it < 4; it++) {
            float comp[4] = {v[it].x, v[it].y, v[it].z, v[it].w};
            #pragma unroll
            for (int c = 0; c < 4; c++) {
                unsigned u = ordf(comp[c]);
                bool pred = (u >= ut);
                unsigned bal = __ballot_sync(0xffffffffu, pred);
                int base = 0;
                if (lane == 0 && bal) base = (int)atomicAdd(&scnt[1], (unsigned)__popc(bal));
                base = __shfl_sync(0xffffffffu, base, 0);
                if (pred) {
                    int pos = base + __popc(bal & ((1u << lane) - 1u));
                    idxs[pos] = (tid + it*256)*4 + c;
                    wts[pos]  = __expf(comp[c] - m);
                }
            }
        }
    } else {
        // boundary ties: strictly-greater first, then lowest-index equals
        #pragma unroll
        for (int it = 0; it < 4; it++) {
            float comp[4] = {v[it].x, v[it].y, v[it].z, v[it].w};
            #pragma unroll
            for (int c = 0; c < 4; c++) {
                unsigned u = ordf(comp[c]);
                bool pg = (u > ut), pe = (u == ut);
                unsigned balg = __ballot_sync(0xffffffffu, pg);
                int baseg = 0;
                if (lane == 0 && balg) baseg = (int)atomicAdd(&scnt[1], (unsigned)__popc(balg));
                baseg = __shfl_sync(0xffffffffu, baseg, 0);
                if (pg) {
                    int pos = baseg + __popc(balg & ((1u << lane) - 1u));
                    idxs[pos] = (tid + it*256)*4 + c;
                    wts[pos]  = __expf(comp[c] - m);
                }
                unsigned bale = __ballot_sync(0xffffffffu, pe);
                int basee = 0;
                if (lane == 0 && bale) basee = (int)atomicAdd(&scnt[2], (unsigned)__popc(bale));
                basee = __shfl_sync(0xffffffffu, basee, 0);
                if (pe) {
                    int pos = basee + __popc(bale & ((1u << lane) - 1u));
                    if (pos < 256) eqidx[pos] = (tid + it*256)*4 + c;
                }
            }
        }
        __syncthreads();
        if (tid == 0) {
            int ecnt = (int)scnt[2]; if (ecnt > 256) ecnt = 256;
            float wt_eq = __expf(iordf(ut) - m);
            int base = TK_ - need;
            for (int a = 0; a < need; a++) {
                int bm2 = 0x7FFFFFFF, bi = -1;
                for (int e2 = 0; e2 < ecnt; e2++)
                    if (eqidx[e2] < bm2) { bm2 = eqidx[e2]; bi = e2; }
                eqidx[bi] = 0x7FFFFFFF;
                idxs[base + a] = bm2;
                wts[base + a] = wt_eq;
            }
        }
    }
    __syncthreads();

    // ---- AV over 256 selected: 32 entries per warp, lane = head dim ----
    float acc = 0.f, wsum = 0.f;
    int e0 = w * 32;
    #pragma unroll 4
    for (int e = e0; e < e0 + 32; e++) {
        int j = idxs[e];
        float wt = wts[e];
        acc  += wt * vp[(size_t)j*HD_ + lane];
        wsum += wt;
    }
    racc[w*HD_ + lane] = acc;
    if (lane == 0) rws[w] = wsum;
    __syncthreads();
    if (w == 0) {
        float a = 0.f, ws = 0.f;
        #pragma unroll
        for (int q = 0; q < 8; q++) { a += racc[q*HD_ + lane]; ws += rws[q]; }
        int head = bh & 3, bb = bh >> 2;
        g_att[((size_t)(bb*C_ + head*HD_ + lane)) * N_ + n] = a / ws;
    }
}

// ================= proj + residual =================
__global__ void __launch_bounds__(256) proj_kernel(const float* __restrict__ x,
                                                   const float* __restrict__ W,
                                                   const float* __restrict__ bias,
                                                   float* __restrict__ out) {
    __shared__ float as_[C_*64];
    int n0 = blockIdx.x * 64, bb = blockIdx.y;
    int tid = threadIdx.x;
    const float* ap = g_att + (size_t)bb * C_ * N_;
    for (int i = tid; i < C_*64; i += 256) {
        int c = i >> 6, nl = i & 63;
        as_[i] = ap[(size_t)c*N_ + n0 + nl];
    }
    __syncthreads();

    int nq = tid & 3, og = tid >> 2;
    float acc[2][16];
    #pragma unroll
    for (int k = 0; k < 2; k++)
        #pragma unroll
        for (int j = 0; j < 16; j++) acc[k][j] = 0.f;

    const float4* as4 = (const float4*)as_;
    for (int c = 0; c < C_; c++) {
        float4 h0 = as4[c*16 + nq*4 + 0];
        float4 h1 = as4[c*16 + nq*4 + 1];
        float4 h2 = as4[c*16 + nq*4 + 2];
        float4 h3 = as4[c*16 + nq*4 + 3];
        float hv[16] = {h0.x,h0.y,h0.z,h0.w, h1.x,h1.y,h1.z,h1.w,
                        h2.x,h2.y,h2.z,h2.w, h3.x,h3.y,h3.z,h3.w};
        #pragma unroll
        for (int k = 0; k < 2; k++) {
            float wv = W[(size_t)(og + 64*k)*C_ + c];
            #pragma unroll
            for (int j = 0; j < 16; j++) acc[k][j] += wv * hv[j];
        }
    }
    #pragma unroll
    for (int k = 0; k < 2; k++) {
        int o = og + 64*k;
        float bv = bias[o];
        size_t base = ((size_t)bb*C_ + o)*N_ + n0 + nq*16;
        #pragma unroll
        for (int j4 = 0; j4 < 4; j4++) {
            float4 xi = *(const float4*)&x[base + j4*4];
            float4 r;
            r.x = acc[k][j4*4+0] + bv + xi.x;
            r.y = acc[k][j4*4+1] + bv + xi.y;
            r.z = acc[k][j4*4+2] + bv + xi.z;
            r.w = acc[k][j4*4+3] + bv + xi.w;
            *(float4*)&out[base + j4*4] = r;
        }
    }
}

// ================= launch =================
extern "C" void kernel_launch(void* const* d_in, const int* in_sizes, int n_in,
                              void* d_out, int out_size) {
    const float* x      = (const float*)d_in[0];
    const float* gn_w   = (const float*)d_in[1];
    const float* gn_b   = (const float*)d_in[2];
    const float* qkv_w  = (const float*)d_in[3];
    const float* qkv_b  = (const float*)d_in[4];
    const float* proj_w = (const float*)d_in[5];
    const float* proj_b = (const float*)d_in[6];
    float* out = (float*)d_out;

    gn_kernel    <<<B_*GR_, 256>>>(x, gn_w, gn_b);
    qkv_kernel   <<<dim3(N_/64, B_), 256>>>(qkv_w, qkv_b);
    score_kernel <<<dim3(N_/128, N_/128, B_*NH_), 256>>>();
    select_kernel<<<dim3(N_, B_*NH_), 256>>>();
    proj_kernel  <<<dim3(N_/64, B_), 256>>>(x, proj_w, proj_b, out);
}